// round 1
// baseline (speedup 1.0000x reference)
#include <cuda_runtime.h>

// BinaryLSTM: B=64, T=1024, D=128, H=512, C=2
// Persistent column-parallel LSTM kernel + head kernel.

#define BB   64
#define TT   1024
#define DD   128
#define HH   512
#define G4   2048
#define NCLS 2
#define NCTA 128          // persistent CTAs (<=148 SMs, 1 CTA/SM due to smem)
#define NTHR 256
#define HS   4            // h-columns per CTA
#define NCOL 16           // gate columns per CTA (4 gates x HS)
#define HPAD 65           // smem row pad (stride 65 -> conflict-free)
#define XPAD 65

#define SMEM_FLOATS (HH*HPAD + DD*XPAD + HH*NCOL + DD*NCOL + BB*NCOL + NCOL + 16)
#define SMEM_BYTES  (SMEM_FLOATS * 4)

// ---- device scratch (static allocation: allowed) ----
__device__ float g_h[2][BB][HH];                 // double-buffered hidden state
__device__ float g_hs[(size_t)BB * TT * HH];     // all hidden states [B][T][H], 128 MB
__device__ unsigned g_bar_count;                 // grid barrier arrive counter
__device__ volatile unsigned g_bar_phase;        // grid barrier phase (monotonic)

// Sense-free monotonic grid barrier. Phase is compared relative to the value
// read at kernel entry, so repeated graph replays work (count self-resets).
__device__ __forceinline__ void grid_barrier(unsigned target) {
    __syncthreads();
    if (threadIdx.x == 0) {
        __threadfence();
        unsigned old = atomicAdd(&g_bar_count, 1u);
        if (old == NCTA - 1) {
            atomicExch(&g_bar_count, 0u);
            __threadfence();
            g_bar_phase = target;
        } else {
            while ((int)(g_bar_phase - target) < 0) { }
        }
        __threadfence();
    }
    __syncthreads();
}

__device__ __forceinline__ float fast_sigmoid(float z) {
    return 1.f / (1.f + __expf(-z));
}
// NaN-safe tanh via exp (avoids inf/inf for large |z|)
__device__ __forceinline__ float fast_tanh(float z) {
    float az = fabsf(z);
    float e  = __expf(-2.f * az);
    float t  = (1.f - e) / (1.f + e);
    return copysignf(t, z);
}

__global__ void __launch_bounds__(NTHR, 1)
lstm_persistent_kernel(const float* __restrict__ x,
                       const float* __restrict__ Wx,
                       const float* __restrict__ Wh,
                       const float* __restrict__ bias,
                       float* __restrict__ d_cost)
{
    extern __shared__ float sm[];
    float* h_s = sm;                       // [HH][HPAD] transposed h: h_s[k*HPAD+b]
    float* x_s = h_s + HH * HPAD;          // [DD][XPAD] transposed x_t
    float* whs = x_s + DD * XPAD;          // [HH][NCOL] stationary Wh slice
    float* wxs = whs + HH * NCOL;          // [DD][NCOL] stationary Wx slice
    float* z_s = wxs + DD * NCOL;          // [BB][NCOL] gate pre-activations
    float* bss = z_s + BB * NCOL;          // [NCOL] bias slice
    unsigned* pb = (unsigned*)(bss + NCOL);

    const int tid = threadIdx.x;
    const int cta = blockIdx.x;
    const int hc0 = cta * HS;              // first h-column owned by this CTA

    if (cta == 0 && tid == 0) *d_cost = 0.f;   // d_out cost slot (poisoned by harness)

    // ---- load stationary weight slices ----
    // local column cc = gate*4 + jj  ->  global gate column gate*HH + hc0 + jj
    for (int i = tid; i < HH * NCOL; i += NTHR) {
        int k = i >> 4, cc = i & 15;
        whs[i] = Wh[k * G4 + (cc >> 2) * HH + hc0 + (cc & 3)];
    }
    for (int i = tid; i < DD * NCOL; i += NTHR) {
        int k = i >> 4, cc = i & 15;
        wxs[i] = Wx[k * G4 + (cc >> 2) * HH + hc0 + (cc & 3)];
    }
    if (tid < NCOL) bss[tid] = bias[(tid >> 2) * HH + hc0 + (tid & 3)];
    if (tid == 0) *pb = g_bar_phase;       // capture barrier phase base

    const int bb = tid >> 2;               // batch row owned (0..63)
    const int q  = tid & 3;                // gate index for phase 2, col group for phase 1
    g_h[0][bb][hc0 + q] = 0.f;             // zero h0 for our columns
    __syncthreads();
    unsigned bar_t = *pb;
    const float b0 = bss[4*q+0], b1 = bss[4*q+1], b2 = bss[4*q+2], b3 = bss[4*q+3];

    grid_barrier(++bar_t);                 // h0 zeroing visible everywhere

    float c_state = 0.f;                   // cell state for (bb, hc0+q), lives in reg
    int cur = 0;
    for (int s = 0; s < TT; ++s) {
        // ---- stage x_t (transposed) ----
        for (int i = tid; i < BB * DD; i += NTHR) {
            int bl = i >> 7, d = i & (DD - 1);
            x_s[d * XPAD + bl] = x[((size_t)bl * TT + s) * DD + d];
        }
        // ---- stage h_prev (transposed); MUST bypass L1 (cross-SM producer) ----
        const float* hg = &g_h[cur][0][0];
        for (int i = tid; i < BB * HH; i += NTHR) {
            int bl = i >> 9, k = i & (HH - 1);
            h_s[k * HPAD + bl] = __ldcg(hg + i);
        }
        __syncthreads();

        // ---- z[bb][4q..4q+3] = bias + x_t.Wx + h.Wh ----
        float a0 = b0, a1 = b1, a2 = b2, a3 = b3;
        {
            const float*  hp = h_s + bb;
            const float4* wp = (const float4*)whs + q;
            #pragma unroll 8
            for (int k = 0; k < HH; ++k) {
                float  hv = hp[k * HPAD];          // broadcast across 4 lanes
                float4 w  = wp[k * 4];
                a0 += hv * w.x; a1 += hv * w.y; a2 += hv * w.z; a3 += hv * w.w;
            }
            const float*  xp = x_s + bb;
            const float4* wq = (const float4*)wxs + q;
            #pragma unroll 8
            for (int d = 0; d < DD; ++d) {
                float  xv = xp[d * XPAD];
                float4 w  = wq[d * 4];
                a0 += xv * w.x; a1 += xv * w.y; a2 += xv * w.z; a3 += xv * w.w;
            }
        }
        ((float4*)(z_s + bb * NCOL))[q] = make_float4(a0, a1, a2, a3);
        __syncthreads();

        // ---- gates: thread (bb, jj=q) combines i,f,g,o for its h-column ----
        float zi = z_s[bb * NCOL +      q];
        float zf = z_s[bb * NCOL +  4 + q];
        float zg = z_s[bb * NCOL +  8 + q];
        float zo = z_s[bb * NCOL + 12 + q];
        float ig = fast_sigmoid(zi), fg = fast_sigmoid(zf);
        float gg = fast_tanh(zg),    og = fast_sigmoid(zo);
        c_state  = fg * c_state + ig * gg;
        float hn = og * fast_tanh(c_state);
        __stcg(&g_h[cur ^ 1][bb][hc0 + q], hn);                    // L1-bypass write
        g_hs[((size_t)bb * TT + s) * HH + hc0 + q] = hn;           // for head kernel

        grid_barrier(++bar_t);
        cur ^= 1;
    }
}

// Head: logits = hs @ Wo + bo (C=2), softmax probs -> d_out, mean NLL -> d_cost.
// One warp per (b,t).
__global__ void __launch_bounds__(256)
head_kernel(const int* __restrict__ labels,
            const float* __restrict__ Wo,
            const float* __restrict__ bo,
            float* __restrict__ out,
            float* __restrict__ d_cost)
{
    __shared__ float part[8];
    int warp = threadIdx.x >> 5, lane = threadIdx.x & 31;
    int bt   = blockIdx.x * 8 + warp;          // bt = b*T + t
    const float* hrow = g_hs + (size_t)bt * HH;

    float s0 = 0.f, s1 = 0.f;
    #pragma unroll 4
    for (int k = lane; k < HH; k += 32) {
        float  h = hrow[k];
        float2 w = ((const float2*)Wo)[k];
        s0 += h * w.x; s1 += h * w.y;
    }
    #pragma unroll
    for (int off = 16; off; off >>= 1) {
        s0 += __shfl_xor_sync(0xffffffffu, s0, off);
        s1 += __shfl_xor_sync(0xffffffffu, s1, off);
    }
    if (lane == 0) {
        float l0 = s0 + bo[0], l1 = s1 + bo[1];
        float m  = fmaxf(l0, l1);
        float e0 = __expf(l0 - m), e1 = __expf(l1 - m);
        float Z  = e0 + e1;
        float inv = 1.f / Z;
        ((float2*)out)[bt] = make_float2(e0 * inv, e1 * inv);
        int lab = labels[bt];
        float llab = lab ? l1 : l0;
        part[warp] = -(llab - m - __logf(Z));
    }
    __syncthreads();
    if (threadIdx.x == 0) {
        float sum = 0.f;
        #pragma unroll
        for (int w = 0; w < 8; ++w) sum += part[w];
        atomicAdd(d_cost, sum * (1.f / (float)(BB * TT)));
    }
}

extern "C" void kernel_launch(void* const* d_in, const int* in_sizes, int n_in,
                              void* d_out, int out_size)
{
    (void)in_sizes; (void)n_in; (void)out_size;
    const float* x      = (const float*)d_in[0];
    const int*   labels = (const int*)  d_in[1];
    const float* Wx     = (const float*)d_in[2];
    const float* Wh     = (const float*)d_in[3];
    const float* b      = (const float*)d_in[4];
    const float* Wo     = (const float*)d_in[5];
    const float* bo     = (const float*)d_in[6];
    float* out    = (float*)d_out;
    float* d_cost = out + (size_t)BB * TT * NCLS;   // cost appended after probs

    cudaFuncSetAttribute(lstm_persistent_kernel,
                         cudaFuncAttributeMaxDynamicSharedMemorySize, SMEM_BYTES);

    lstm_persistent_kernel<<<NCTA, NTHR, SMEM_BYTES>>>(x, Wx, Wh, b, d_cost);
    head_kernel<<<(BB * TT) / 8, 256>>>(labels, Wo, bo, out, d_cost);
}

// round 6
// speedup vs baseline: 1.4479x; 1.4479x over previous
#include <cuda_runtime.h>
#include <cstdint>

// BinaryLSTM: B=64, T=1024, D=128, H=512, C=2
// Persistent column-parallel LSTM (f32x2 FMA + cp.async staging + tree barrier)

#define BB   64
#define TT   1024
#define DD   128
#define HH   512
#define G4   2048
#define NCLS 2
#define NCTA 128
#define NTHR 256
#define HROW 516      // smem row stride (floats): mod32=4 -> conflict-free, 16B-mult
#define XROW 132
#define ZROW 20
#define NCOL 16       // gate columns per CTA (4 gates x 4 h-cols)

#define SMEM_FLOATS (BB*HROW + BB*XROW + HH*NCOL + DD*NCOL + BB*ZROW + NCOL + 16)
#define SMEM_BYTES  (SMEM_FLOATS * 4)

typedef unsigned long long ull;

// ---- device scratch ----
__device__ float g_h[2][BB][HH];                 // double-buffered hidden state
__device__ float g_hs[(size_t)BB * TT * HH];     // all hidden states [B][T][H]
__device__ unsigned g_sub[8 * 32];               // tree barrier sub-counters, 128B apart
__device__ unsigned g_root;
__device__ volatile unsigned g_phase;            // monotonic phase

// ---- PTX helpers ----
__device__ __forceinline__ ull fma2(ull a, ull b, ull c) {
    ull d; asm("fma.rn.f32x2 %0, %1, %2, %3;" : "=l"(d) : "l"(a), "l"(b), "l"(c));
    return d;
}
__device__ __forceinline__ ull dup2(float x) {
    ull d; asm("mov.b64 %0, {%1, %1};" : "=l"(d) : "f"(x)); return d;
}
__device__ __forceinline__ ull pk2(float lo, float hi) {
    ull d; asm("mov.b64 %0, {%1, %2};" : "=l"(d) : "f"(lo), "f"(hi)); return d;
}
__device__ __forceinline__ uint32_t sa(const void* p) {
    return (uint32_t)__cvta_generic_to_shared(p);
}
__device__ __forceinline__ void cp16(uint32_t s, const void* g) {
    asm volatile("cp.async.cg.shared.global [%0], [%1], 16;" :: "r"(s), "l"(g));
}
__device__ __forceinline__ void cp_wait_all() {
    asm volatile("cp.async.commit_group;\ncp.async.wait_group 0;" ::: "memory");
}

// Two-level monotonic grid barrier (128 CTAs: 8 groups x 16).
// Phase releases only after all 128 arrivals, so next-phase arrivals can't mix.
__device__ __forceinline__ void grid_barrier(unsigned target, int cta) {
    __threadfence();                       // release: order h stores before arrive
    __syncthreads();
    if (threadIdx.x == 0) {
        unsigned grp = (unsigned)cta & 7u;
        unsigned old = atomicAdd(&g_sub[grp * 32], 1u);
        if ((old & 15u) == 15u) {
            unsigned r = atomicAdd(&g_root, 1u);
            if ((r & 7u) == 7u) g_phase = target;
        }
        while ((int)(g_phase - target) < 0) { }
        __threadfence();                   // acquire
    }
    __syncthreads();
}

__device__ __forceinline__ float fast_sigmoid(float z) {
    return 1.f / (1.f + __expf(-z));
}
__device__ __forceinline__ float fast_tanh(float z) {
    float az = fabsf(z);
    float e  = __expf(-2.f * az);
    float t  = (1.f - e) / (1.f + e);
    return copysignf(t, z);
}

__global__ void __launch_bounds__(NTHR, 1)
lstm_persistent_kernel(const float* __restrict__ x,
                       const float* __restrict__ Wx,
                       const float* __restrict__ Wh,
                       const float* __restrict__ bias,
                       float* __restrict__ d_cost)
{
    extern __shared__ float sm[];
    float* h_s = sm;                      // [BB][HROW]  h_prev rows (natural layout)
    float* x_s = h_s + BB * HROW;         // [BB][XROW]  x_t rows
    float* whs = x_s + BB * XROW;         // [HH][NCOL]  stationary Wh slice
    float* wxs = whs + HH * NCOL;         // [DD][NCOL]  stationary Wx slice
    float* z_s = wxs + DD * NCOL;         // [BB][ZROW]  gate pre-activations
    float* bss = z_s + BB * ZROW;         // [NCOL]
    unsigned* pb = (unsigned*)(bss + NCOL);

    const int tid = threadIdx.x;
    const int cta = blockIdx.x;
    const int hc0 = cta * 4;              // first h-column owned by this CTA

    if (cta == 0 && tid == 0) *d_cost = 0.f;

    // stationary weight slices: local col cc = gate*4 + j -> Wh col gate*HH + hc0 + j
    for (int i = tid; i < HH * NCOL; i += NTHR) {
        int k = i >> 4, cc = i & 15;
        whs[i] = Wh[k * G4 + (cc >> 2) * HH + hc0 + (cc & 3)];
    }
    for (int i = tid; i < DD * NCOL; i += NTHR) {
        int k = i >> 4, cc = i & 15;
        wxs[i] = Wx[k * G4 + (cc >> 2) * HH + hc0 + (cc & 3)];
    }
    if (tid < NCOL) bss[tid] = bias[(tid >> 2) * HH + hc0 + (tid & 3)];
    if (tid == 0) *pb = g_phase;

    const int bb = tid >> 2;              // batch row owned (0..63)
    const int q  = tid & 3;               // gate (phase1) / h-col (phase2)
    __stcg(&g_h[0][bb][hc0 + q], 0.f);    // zero h0 for our columns (to L2)
    __syncthreads();
    unsigned bar_t = *pb;
    const ull bias01 = pk2(bss[4*q+0], bss[4*q+1]);
    const ull bias23 = pk2(bss[4*q+2], bss[4*q+3]);

    grid_barrier(++bar_t, cta);           // h0 visible everywhere

    const float* hrow = h_s + bb * HROW;
    const float* xrow = x_s + bb * XROW;
    // Row k of whs = 16 floats = 4 ulonglong2. Thread's 4 cols (4q..4q+3) at
    // ull2 index 4*k + q  ->  base (ull2*)whs + q, stride 4 per row.   [R2 bug: was 2*k]
    const ulonglong2* wh2 = (const ulonglong2*)whs + q;
    const ulonglong2* wx2 = (const ulonglong2*)wxs + q;

    float c_state = 0.f;
    int cur = 0;
    for (int s = 0; s < TT; ++s) {
        // ---- staging via cp.async (.cg = L2-coherent with __stcg producers) ----
        const char* hg = (const char*)&g_h[cur][0][0];
        #pragma unroll
        for (int c = tid; c < (BB * HH * 4) / 16; c += NTHR) {     // 32 chunks/thread
            int row = c >> 7, off = (c & 127) << 4;
            cp16(sa(h_s + row * HROW) + (unsigned)off, hg + row * (HH * 4) + off);
        }
        #pragma unroll
        for (int c = tid; c < (BB * DD * 4) / 16; c += NTHR) {     // 8 chunks/thread
            int row = c >> 5, off = (c & 31) << 4;
            cp16(sa(x_s + row * XROW) + (unsigned)off,
                 (const char*)x + ((size_t)row * TT + s) * (DD * 4) + off);
        }
        cp_wait_all();
        __syncthreads();

        // ---- z[bb][4q..4q+3] = bias + h.Wh + x.Wx  (f32x2 packed FMA) ----
        ull a01 = bias01, a23 = bias23;
        #pragma unroll 8
        for (int k = 0; k < HH; k += 2) {
            float2 h2 = *(const float2*)(hrow + k);
            ull hk  = dup2(h2.x);
            ull hk1 = dup2(h2.y);
            ulonglong2 w0 = wh2[4 * k];          // row k,   cols 4q..4q+3
            ulonglong2 w1 = wh2[4 * k + 4];      // row k+1, cols 4q..4q+3
            a01 = fma2(hk,  w0.x, a01);  a23 = fma2(hk,  w0.y, a23);
            a01 = fma2(hk1, w1.x, a01);  a23 = fma2(hk1, w1.y, a23);
        }
        #pragma unroll 8
        for (int d = 0; d < DD; d += 2) {
            float2 x2 = *(const float2*)(xrow + d);
            ull xk  = dup2(x2.x);
            ull xk1 = dup2(x2.y);
            ulonglong2 w0 = wx2[4 * d];
            ulonglong2 w1 = wx2[4 * d + 4];
            a01 = fma2(xk,  w0.x, a01);  a23 = fma2(xk,  w0.y, a23);
            a01 = fma2(xk1, w1.x, a01);  a23 = fma2(xk1, w1.y, a23);
        }
        {   // store gate-q's 4 columns: z_s[bb][4q + j]
            ull* zp = (ull*)(z_s + bb * ZROW + 4 * q);
            zp[0] = a01; zp[1] = a23;
        }
        __syncthreads();

        // ---- gates: thread (bb, q) combines i,f,g,o for h-col hc0+q ----
        float zi = z_s[bb * ZROW +      q];
        float zf = z_s[bb * ZROW +  4 + q];
        float zg = z_s[bb * ZROW +  8 + q];
        float zo = z_s[bb * ZROW + 12 + q];
        float ig = fast_sigmoid(zi), fg = fast_sigmoid(zf);
        float gg = fast_tanh(zg),    og = fast_sigmoid(zo);
        c_state  = fg * c_state + ig * gg;
        float hn = og * fast_tanh(c_state);
        __stcg(&g_h[cur ^ 1][bb][hc0 + q], hn);
        g_hs[((size_t)bb * TT + s) * HH + hc0 + q] = hn;

        grid_barrier(++bar_t, cta);
        cur ^= 1;
    }
}

// Head: logits = hs @ Wo + bo (C=2), softmax -> out, mean NLL -> d_cost.
__global__ void __launch_bounds__(256)
head_kernel(const int* __restrict__ labels,
            const float* __restrict__ Wo,
            const float* __restrict__ bo,
            float* __restrict__ out,
            float* __restrict__ d_cost)
{
    __shared__ float part[8];
    int warp = threadIdx.x >> 5, lane = threadIdx.x & 31;
    int bt   = blockIdx.x * 8 + warp;
    const float* hrow = g_hs + (size_t)bt * HH;

    float s0 = 0.f, s1 = 0.f;
    #pragma unroll 4
    for (int k = lane; k < HH; k += 32) {
        float  h = hrow[k];
        float2 w = ((const float2*)Wo)[k];
        s0 += h * w.x; s1 += h * w.y;
    }
    #pragma unroll
    for (int off = 16; off; off >>= 1) {
        s0 += __shfl_xor_sync(0xffffffffu, s0, off);
        s1 += __shfl_xor_sync(0xffffffffu, s1, off);
    }
    if (lane == 0) {
        float l0 = s0 + bo[0], l1 = s1 + bo[1];
        float m  = fmaxf(l0, l1);
        float e0 = __expf(l0 - m), e1 = __expf(l1 - m);
        float Z  = e0 + e1;
        float inv = 1.f / Z;
        ((float2*)out)[bt] = make_float2(e0 * inv, e1 * inv);
        int lab = labels[bt];
        float llab = lab ? l1 : l0;
        part[warp] = -(llab - m - __logf(Z));
    }
    __syncthreads();
    if (threadIdx.x == 0) {
        float sum = 0.f;
        #pragma unroll
        for (int w = 0; w < 8; ++w) sum += part[w];
        atomicAdd(d_cost, sum * (1.f / (float)(BB * TT)));
    }
}

extern "C" void kernel_launch(void* const* d_in, const int* in_sizes, int n_in,
                              void* d_out, int out_size)
{
    (void)in_sizes; (void)n_in; (void)out_size;
    const float* x      = (const float*)d_in[0];
    const int*   labels = (const int*)  d_in[1];
    const float* Wx     = (const float*)d_in[2];
    const float* Wh     = (const float*)d_in[3];
    const float* b      = (const float*)d_in[4];
    const float* Wo     = (const float*)d_in[5];
    const float* bo     = (const float*)d_in[6];
    float* out    = (float*)d_out;
    float* d_cost = out + (size_t)BB * TT * NCLS;

    cudaFuncSetAttribute(lstm_persistent_kernel,
                         cudaFuncAttributeMaxDynamicSharedMemorySize, SMEM_BYTES);

    lstm_persistent_kernel<<<NCTA, NTHR, SMEM_BYTES>>>(x, Wx, Wh, b, d_cost);
    head_kernel<<<(BB * TT) / 8, 256>>>(labels, Wo, bo, out, d_cost);
}